// round 1
// baseline (speedup 1.0000x reference)
#include <cuda_runtime.h>
#include <cstdint>

// ---------------------------------------------------------------------------
// Problem constants (fixed by the reference: B=4, H=W=64, DIM=512, 8 heads, SR=2)
// ---------------------------------------------------------------------------
#define BATCH   4
#define HH      64
#define WW      64
#define NN      (HH * WW)        // 4096
#define DIMC    512
#define NHEAD   8
#define HD      (DIMC / NHEAD)   // 64
#define SRR     2
#define HP      (HH / SRR)       // 32
#define WP      (WW / SRR)       // 32
#define NP      (HP * WP)        // 1024
#define KSR     (DIMC * SRR * SRR) // 2048

// ---------------------------------------------------------------------------
// Scratch (device globals; no allocation anywhere)
// ---------------------------------------------------------------------------
__device__ float g_P  [(size_t)BATCH * NP * KSR];      // 32 MB  patches
__device__ float g_Xsr[(size_t)BATCH * NP * DIMC];     //  8 MB  conv out / LN out (in-place)
__device__ float g_KV [(size_t)BATCH * NP * 2 * DIMC]; // 16 MB  kv
__device__ float g_Q  [(size_t)BATCH * NN * DIMC];     // 32 MB  q
__device__ float g_O  [(size_t)BATCH * NN * DIMC];     // 32 MB  attention out

__device__ __forceinline__ float* pick_buf(int id) {
    switch (id) {
        case 0: return g_P;
        case 1: return g_Xsr;
        case 2: return g_KV;
        case 3: return g_Q;
        case 4: return g_O;
    }
    return nullptr;
}

// ---------------------------------------------------------------------------
// 1) Gather 2x2 patches: P[b*NP+n', c*4 + ky*2 + kx] = x[b, (2i+ky)*W + 2j+kx, c]
//    One thread per (row, c); writes one float4 (the 4 taps are contiguous cols).
// ---------------------------------------------------------------------------
__global__ void __launch_bounds__(256) gather_patches(const float* __restrict__ x) {
    int t = blockIdx.x * blockDim.x + threadIdx.x;   // (m, c)
    if (t >= BATCH * NP * DIMC) return;
    int c  = t % DIMC;
    int m  = t / DIMC;
    int b  = m / NP;
    int np = m % NP;
    int i  = np / WP, j = np % WP;
    const float* xb = x + (size_t)b * NN * DIMC;
    float4 v;
    v.x = xb[((size_t)((2 * i + 0) * WW + 2 * j + 0)) * DIMC + c];
    v.y = xb[((size_t)((2 * i + 0) * WW + 2 * j + 1)) * DIMC + c];
    v.z = xb[((size_t)((2 * i + 1) * WW + 2 * j + 0)) * DIMC + c];
    v.w = xb[((size_t)((2 * i + 1) * WW + 2 * j + 1)) * DIMC + c];
    *(float4*)&g_P[(size_t)m * KSR + (size_t)c * 4] = v;
}

// ---------------------------------------------------------------------------
// 2) Tiled SGEMM:  C[M,Nc] = A[M,K] @ W[Nc,K]^T (+ bias)
//    64x64 block tile, BK=16, 256 threads, 4x4 micro-tile per thread.
//    A/C may come from device scratch (selected by id) or external pointers.
// ---------------------------------------------------------------------------
__global__ void __launch_bounds__(256) sgemm_xwT(
    int Aid, const float* __restrict__ Aext,
    const float* __restrict__ Wt,
    const float* __restrict__ bias,
    int Cid, float* __restrict__ Cext,
    int M, int Nc, int K)
{
    const float* A = Aext ? Aext : pick_buf(Aid);
    float*       C = Cext ? Cext : pick_buf(Cid);

    __shared__ float As[16][64];
    __shared__ float Bs[16][64];

    const int tid = threadIdx.x;
    const int m0 = blockIdx.y * 64;
    const int n0 = blockIdx.x * 64;
    const int lr = tid >> 2;          // 0..63
    const int lc = (tid & 3) << 2;    // 0,4,8,12
    const int ty = tid >> 4;          // 0..15
    const int tx = tid & 15;          // 0..15

    float acc[4][4];
#pragma unroll
    for (int i = 0; i < 4; i++)
#pragma unroll
        for (int j = 0; j < 4; j++) acc[i][j] = 0.f;

    const float* Aptr = A  + (size_t)(m0 + lr) * K + lc;
    const float* Bptr = Wt + (size_t)(n0 + lr) * K + lc;

    for (int k0 = 0; k0 < K; k0 += 16) {
        float4 a = *(const float4*)(Aptr + k0);
        float4 b = *(const float4*)(Bptr + k0);
        As[lc + 0][lr] = a.x; As[lc + 1][lr] = a.y;
        As[lc + 2][lr] = a.z; As[lc + 3][lr] = a.w;
        Bs[lc + 0][lr] = b.x; Bs[lc + 1][lr] = b.y;
        Bs[lc + 2][lr] = b.z; Bs[lc + 3][lr] = b.w;
        __syncthreads();
#pragma unroll
        for (int k = 0; k < 16; k++) {
            float4 av = *(const float4*)&As[k][ty << 2];
            float4 bv = *(const float4*)&Bs[k][tx << 2];
            float ar[4] = {av.x, av.y, av.z, av.w};
            float br[4] = {bv.x, bv.y, bv.z, bv.w};
#pragma unroll
            for (int i = 0; i < 4; i++)
#pragma unroll
                for (int j = 0; j < 4; j++)
                    acc[i][j] = fmaf(ar[i], br[j], acc[i][j]);
        }
        __syncthreads();
    }

#pragma unroll
    for (int i = 0; i < 4; i++) {
        int m = m0 + (ty << 2) + i;
        int n = n0 + (tx << 2);
        float4 v = make_float4(acc[i][0], acc[i][1], acc[i][2], acc[i][3]);
        if (bias) {
            float4 bb = *(const float4*)&bias[n];
            v.x += bb.x; v.y += bb.y; v.z += bb.z; v.w += bb.w;
        }
        *(float4*)&C[(size_t)m * Nc + n] = v;
    }
}

// ---------------------------------------------------------------------------
// 3) LayerNorm in-place on g_Xsr rows (512 wide). One block per row.
// ---------------------------------------------------------------------------
__global__ void __launch_bounds__(128) ln_inplace(const float* __restrict__ gam,
                                                  const float* __restrict__ bet)
{
    float* p = g_Xsr + (size_t)blockIdx.x * DIMC;
    int tid = threadIdx.x;
    float v[4];
    float s = 0.f, sq = 0.f;
#pragma unroll
    for (int i = 0; i < 4; i++) {
        v[i] = p[tid + i * 128];
        s += v[i];
        sq += v[i] * v[i];
    }
#pragma unroll
    for (int o = 16; o > 0; o >>= 1) {
        s  += __shfl_xor_sync(0xffffffffu, s,  o);
        sq += __shfl_xor_sync(0xffffffffu, sq, o);
    }
    __shared__ float ss[4], sqs[4];
    int wid = tid >> 5, lid = tid & 31;
    if (lid == 0) { ss[wid] = s; sqs[wid] = sq; }
    __syncthreads();
    s  = ss[0] + ss[1] + ss[2] + ss[3];
    sq = sqs[0] + sqs[1] + sqs[2] + sqs[3];
    float mu  = s * (1.f / DIMC);
    float var = sq * (1.f / DIMC) - mu * mu;
    float inv = rsqrtf(var + 1e-5f);
#pragma unroll
    for (int i = 0; i < 4; i++) {
        int c = tid + i * 128;
        p[c] = (v[i] - mu) * inv * gam[c] + bet[c];
    }
}

// ---------------------------------------------------------------------------
// 4) Flash attention (fp32). Grid (N/128, NHEAD, B), 128 threads.
//    One query row per thread; K/V streamed in 32-row smem tiles (broadcast
//    reads, conflict-free); online softmax.
// ---------------------------------------------------------------------------
__global__ void __launch_bounds__(128) attn_kernel()
{
    const int tid = threadIdx.x;
    const int qr  = blockIdx.x * 128 + tid;
    const int h   = blockIdx.y;
    const int b   = blockIdx.z;

    const float scale = 0.125f;  // d^-0.5, d=64

    const float* qp = &g_Q[((size_t)b * NN + qr) * DIMC + h * HD];
    float q[HD], acc[HD];
#pragma unroll
    for (int i = 0; i < HD; i += 4) {
        float4 t = *(const float4*)&qp[i];
        q[i + 0] = t.x * scale; q[i + 1] = t.y * scale;
        q[i + 2] = t.z * scale; q[i + 3] = t.w * scale;
    }
#pragma unroll
    for (int i = 0; i < HD; i++) acc[i] = 0.f;

    float m = -1e30f, l = 0.f;

    __shared__ float Ks[32][HD];
    __shared__ float Vs[32][HD];

    const float* kvb = &g_KV[(size_t)b * NP * 2 * DIMC];

    for (int t0 = 0; t0 < NP; t0 += 32) {
#pragma unroll
        for (int i = 0; i < 4; i++) {
            int idx4 = tid + i * 128;           // 0..511 float4 slots
            int r   = idx4 >> 4;                // 0..31
            int c4  = (idx4 & 15) << 2;         // 0..60 step 4
            const float* kr = &kvb[(size_t)(t0 + r) * (2 * DIMC) + h * HD + c4];
            *(float4*)&Ks[r][c4] = *(const float4*)kr;
            *(float4*)&Vs[r][c4] = *(const float4*)(kr + DIMC);
        }
        __syncthreads();

        float s[32];
#pragma unroll
        for (int j = 0; j < 32; j++) s[j] = 0.f;
#pragma unroll
        for (int dc = 0; dc < HD; dc++) {
            float qv = q[dc];
#pragma unroll
            for (int j = 0; j < 32; j++)
                s[j] = fmaf(qv, Ks[j][dc], s[j]);
        }

        float mt = m;
#pragma unroll
        for (int j = 0; j < 32; j++) mt = fmaxf(mt, s[j]);
        float corr = __expf(m - mt);
        m = mt;
        l *= corr;
#pragma unroll
        for (int dc = 0; dc < HD; dc++) acc[dc] *= corr;

#pragma unroll
        for (int j = 0; j < 32; j++) {
            float p = __expf(s[j] - m);
            l += p;
#pragma unroll
            for (int dc = 0; dc < HD; dc++)
                acc[dc] = fmaf(p, Vs[j][dc], acc[dc]);
        }
        __syncthreads();
    }

    float invl = 1.f / l;
    float* op = &g_O[((size_t)b * NN + qr) * DIMC + h * HD];
#pragma unroll
    for (int i = 0; i < HD; i += 4) {
        float4 t = make_float4(acc[i] * invl, acc[i + 1] * invl,
                               acc[i + 2] * invl, acc[i + 3] * invl);
        *(float4*)&op[i] = t;
    }
}

// ---------------------------------------------------------------------------
// Launch. Inputs (metadata order):
//  0:x [4,4096,512] f32   1:H i32   2:W i32   3:Wq [512,512]   4:Wkv [1024,512]
//  5:Wsr [512,512,2,2]    6:bsr[512] 7:ln_g[512] 8:ln_b[512]  9:Wp [512,512]
// 10:bp[512];   out: [4,4096,512] f32
// ---------------------------------------------------------------------------
extern "C" void kernel_launch(void* const* d_in, const int* in_sizes, int n_in,
                              void* d_out, int out_size)
{
    const float* x    = (const float*)d_in[0];
    const float* Wq   = (const float*)d_in[3];
    const float* Wkv  = (const float*)d_in[4];
    const float* Wsr  = (const float*)d_in[5];
    const float* bsr  = (const float*)d_in[6];
    const float* ln_g = (const float*)d_in[7];
    const float* ln_b = (const float*)d_in[8];
    const float* Wp   = (const float*)d_in[9];
    const float* bp   = (const float*)d_in[10];
    float* out = (float*)d_out;

    // 1) patches
    gather_patches<<<(BATCH * NP * DIMC + 255) / 256, 256>>>(x);

    // 2) spatial-reduction conv as GEMM: Xsr = P @ Wsr_flat^T + bsr
    sgemm_xwT<<<dim3(DIMC / 64, BATCH * NP / 64), 256>>>(
        0, nullptr, Wsr, bsr, 1, nullptr, BATCH * NP, DIMC, KSR);

    // 3) LayerNorm in place
    ln_inplace<<<BATCH * NP, 128>>>(ln_g, ln_b);

    // 4) KV = Xn @ Wkv^T
    sgemm_xwT<<<dim3(2 * DIMC / 64, BATCH * NP / 64), 256>>>(
        1, nullptr, Wkv, nullptr, 2, nullptr, BATCH * NP, 2 * DIMC, DIMC);

    // 5) Q = x @ Wq^T (independent of 2-4)
    sgemm_xwT<<<dim3(DIMC / 64, BATCH * NN / 64), 256>>>(
        -1, x, Wq, nullptr, 3, nullptr, BATCH * NN, DIMC, DIMC);

    // 6) attention
    attn_kernel<<<dim3(NN / 128, NHEAD, BATCH), 128>>>();

    // 7) out = O @ Wp^T + bp
    sgemm_xwT<<<dim3(DIMC / 64, BATCH * NN / 64), 256>>>(
        4, nullptr, Wp, bp, -1, out, BATCH * NN, DIMC, DIMC);
}

// round 4
// speedup vs baseline: 2.8320x; 2.8320x over previous
#include <cuda_runtime.h>
#include <cstdint>

// ---------------------------------------------------------------------------
// Problem constants (B=4, H=W=64, DIM=512, 8 heads, SR=2)
// ---------------------------------------------------------------------------
#define BATCH   4
#define HH      64
#define WW      64
#define NN      (HH * WW)        // 4096
#define DIMC    512
#define NHEAD   8
#define HD      (DIMC / NHEAD)   // 64
#define SRR     2
#define HP      (HH / SRR)       // 32
#define WP      (WW / SRR)       // 32
#define NP      (HP * WP)        // 1024
#define KSR     (DIMC * SRR * SRR) // 2048

// ---------------------------------------------------------------------------
// Scratch (device globals; no allocation anywhere)
// ---------------------------------------------------------------------------
__device__ float g_P  [(size_t)BATCH * NP * KSR];      // 32 MB  patches
__device__ float g_Xsr[(size_t)BATCH * NP * DIMC];     //  8 MB  conv out / LN out
__device__ float g_KV [(size_t)BATCH * NP * 2 * DIMC]; // 16 MB  kv
__device__ float g_Q  [(size_t)BATCH * NN * DIMC];     // 32 MB  q
__device__ float g_O  [(size_t)BATCH * NN * DIMC];     // 32 MB  attention out

__device__ __forceinline__ float* pick_buf(int id) {
    switch (id) {
        case 0: return g_P;
        case 1: return g_Xsr;
        case 2: return g_KV;
        case 3: return g_Q;
        case 4: return g_O;
    }
    return nullptr;
}

// ---------------------------------------------------------------------------
// mma.sync tf32 helpers (sm_80+ path; works on plain sm_100 target)
// ---------------------------------------------------------------------------
__device__ __forceinline__ uint32_t f2tf32(float x) {
    uint32_t u;
    asm("cvt.rna.tf32.f32 %0, %1;" : "=r"(u) : "f"(x));
    return u;
}

__device__ __forceinline__ void mma1688(float c[4],
                                        uint32_t a0, uint32_t a1,
                                        uint32_t a2, uint32_t a3,
                                        uint32_t b0, uint32_t b1) {
    asm volatile(
        "mma.sync.aligned.m16n8k8.row.col.f32.tf32.tf32.f32 "
        "{%0,%1,%2,%3}, {%4,%5,%6,%7}, {%8,%9}, {%0,%1,%2,%3};"
        : "+f"(c[0]), "+f"(c[1]), "+f"(c[2]), "+f"(c[3])
        : "r"(a0), "r"(a1), "r"(a2), "r"(a3), "r"(b0), "r"(b1));
}

__device__ __forceinline__ uint32_t fbits(float x) { return __float_as_uint(x); }

// ---------------------------------------------------------------------------
// 1) Gather 2x2 patches: P[m, c*4 + ky*2 + kx]
// ---------------------------------------------------------------------------
__global__ void __launch_bounds__(256) gather_patches(const float* __restrict__ x) {
    int t = blockIdx.x * blockDim.x + threadIdx.x;
    if (t >= BATCH * NP * DIMC) return;
    int c  = t % DIMC;
    int m  = t / DIMC;
    int b  = m / NP;
    int np = m % NP;
    int i  = np / WP, j = np % WP;
    const float* xb = x + (size_t)b * NN * DIMC;
    float4 v;
    v.x = xb[((size_t)((2 * i + 0) * WW + 2 * j + 0)) * DIMC + c];
    v.y = xb[((size_t)((2 * i + 0) * WW + 2 * j + 1)) * DIMC + c];
    v.z = xb[((size_t)((2 * i + 1) * WW + 2 * j + 0)) * DIMC + c];
    v.w = xb[((size_t)((2 * i + 1) * WW + 2 * j + 1)) * DIMC + c];
    *(float4*)&g_P[(size_t)m * KSR + (size_t)c * 4] = v;
}

// ---------------------------------------------------------------------------
// 2) mma.sync tf32 GEMM: C[M,Nc] = A[M,K] @ W[Nc,K]^T (+bias)
//    128x128 CTA tile, 256 threads (8 warps, warp tile 32x64), BK=16.
//    Smem [128][20] padding -> conflict-free fragment loads.
// ---------------------------------------------------------------------------
__global__ void __launch_bounds__(256) mma_gemm(
    int Aid, const float* __restrict__ Aext,
    const float* __restrict__ Wt,
    const float* __restrict__ bias,
    int Cid, float* __restrict__ Cext,
    int M, int Nc, int K)
{
    const float* A = Aext ? Aext : pick_buf(Aid);
    float*       C = Cext ? Cext : pick_buf(Cid);

    __shared__ float As[128][20];
    __shared__ float Bs[128][20];

    const int tid  = threadIdx.x;
    const int wid  = tid >> 5;
    const int lane = tid & 31;
    const int g = lane >> 2, t = lane & 3;
    const int wm = (wid & 3) * 32;     // warp M offset in CTA tile
    const int wn = (wid >> 2) * 64;    // warp N offset
    const int m0 = blockIdx.y * 128;
    const int n0 = blockIdx.x * 128;

    float acc[2][8][4];
#pragma unroll
    for (int mt = 0; mt < 2; mt++)
#pragma unroll
        for (int nt = 0; nt < 8; nt++)
#pragma unroll
            for (int c = 0; c < 4; c++) acc[mt][nt][c] = 0.f;

    const int lrow = tid >> 1;         // 0..127
    const int lcol = (tid & 1) * 8;    // 0 or 8

    for (int k0 = 0; k0 < K; k0 += 16) {
        float4 av0 = *(const float4*)&A [(size_t)(m0 + lrow) * K + k0 + lcol];
        float4 av1 = *(const float4*)&A [(size_t)(m0 + lrow) * K + k0 + lcol + 4];
        float4 bv0 = *(const float4*)&Wt[(size_t)(n0 + lrow) * K + k0 + lcol];
        float4 bv1 = *(const float4*)&Wt[(size_t)(n0 + lrow) * K + k0 + lcol + 4];
        As[lrow][lcol + 0] = __uint_as_float(f2tf32(av0.x));
        As[lrow][lcol + 1] = __uint_as_float(f2tf32(av0.y));
        As[lrow][lcol + 2] = __uint_as_float(f2tf32(av0.z));
        As[lrow][lcol + 3] = __uint_as_float(f2tf32(av0.w));
        As[lrow][lcol + 4] = __uint_as_float(f2tf32(av1.x));
        As[lrow][lcol + 5] = __uint_as_float(f2tf32(av1.y));
        As[lrow][lcol + 6] = __uint_as_float(f2tf32(av1.z));
        As[lrow][lcol + 7] = __uint_as_float(f2tf32(av1.w));
        Bs[lrow][lcol + 0] = __uint_as_float(f2tf32(bv0.x));
        Bs[lrow][lcol + 1] = __uint_as_float(f2tf32(bv0.y));
        Bs[lrow][lcol + 2] = __uint_as_float(f2tf32(bv0.z));
        Bs[lrow][lcol + 3] = __uint_as_float(f2tf32(bv0.w));
        Bs[lrow][lcol + 4] = __uint_as_float(f2tf32(bv1.x));
        Bs[lrow][lcol + 5] = __uint_as_float(f2tf32(bv1.y));
        Bs[lrow][lcol + 6] = __uint_as_float(f2tf32(bv1.z));
        Bs[lrow][lcol + 7] = __uint_as_float(f2tf32(bv1.w));
        __syncthreads();

#pragma unroll
        for (int ks = 0; ks < 2; ks++) {
            const int kc = ks * 8 + t;
            uint32_t af[2][4];
#pragma unroll
            for (int mt = 0; mt < 2; mt++) {
                const int r = wm + mt * 16 + g;
                af[mt][0] = fbits(As[r    ][kc    ]);
                af[mt][1] = fbits(As[r + 8][kc    ]);
                af[mt][2] = fbits(As[r    ][kc + 4]);
                af[mt][3] = fbits(As[r + 8][kc + 4]);
            }
#pragma unroll
            for (int nt = 0; nt < 8; nt++) {
                const int br = wn + nt * 8 + g;
                uint32_t b0 = fbits(Bs[br][kc]);
                uint32_t b1 = fbits(Bs[br][kc + 4]);
                mma1688(acc[0][nt], af[0][0], af[0][1], af[0][2], af[0][3], b0, b1);
                mma1688(acc[1][nt], af[1][0], af[1][1], af[1][2], af[1][3], b0, b1);
            }
        }
        __syncthreads();
    }

    // epilogue
#pragma unroll
    for (int mt = 0; mt < 2; mt++) {
        const int mr = m0 + wm + mt * 16 + g;
#pragma unroll
        for (int nt = 0; nt < 8; nt++) {
            const int n = n0 + wn + nt * 8 + 2 * t;
            float bx = 0.f, by = 0.f;
            if (bias) { bx = bias[n]; by = bias[n + 1]; }
            float2 v0 = make_float2(acc[mt][nt][0] + bx, acc[mt][nt][1] + by);
            float2 v1 = make_float2(acc[mt][nt][2] + bx, acc[mt][nt][3] + by);
            *(float2*)&C[(size_t)mr * Nc + n]       = v0;
            *(float2*)&C[(size_t)(mr + 8) * Nc + n] = v1;
        }
    }
}

// ---------------------------------------------------------------------------
// 3) LayerNorm in-place on g_Xsr rows (512 wide)
// ---------------------------------------------------------------------------
__global__ void __launch_bounds__(128) ln_inplace(const float* __restrict__ gam,
                                                  const float* __restrict__ bet)
{
    float* p = g_Xsr + (size_t)blockIdx.x * DIMC;
    int tid = threadIdx.x;
    float v[4];
    float s = 0.f, sq = 0.f;
#pragma unroll
    for (int i = 0; i < 4; i++) {
        v[i] = p[tid + i * 128];
        s += v[i];
        sq += v[i] * v[i];
    }
#pragma unroll
    for (int o = 16; o > 0; o >>= 1) {
        s  += __shfl_xor_sync(0xffffffffu, s,  o);
        sq += __shfl_xor_sync(0xffffffffu, sq, o);
    }
    __shared__ float ss[4], sqs[4];
    int wid = tid >> 5, lid = tid & 31;
    if (lid == 0) { ss[wid] = s; sqs[wid] = sq; }
    __syncthreads();
    s  = ss[0] + ss[1] + ss[2] + ss[3];
    sq = sqs[0] + sqs[1] + sqs[2] + sqs[3];
    float mu  = s * (1.f / DIMC);
    float var = sq * (1.f / DIMC) - mu * mu;
    float inv = rsqrtf(var + 1e-5f);
#pragma unroll
    for (int i = 0; i < 4; i++) {
        int c = tid + i * 128;
        p[c] = (v[i] - mu) * inv * gam[c] + bet[c];
    }
}

// ---------------------------------------------------------------------------
// 4) Flash attention on mma.sync tf32 (FA2-style fragments)
//    Grid (NN/128, NHEAD, BATCH), 256 threads = 8 warps, 16 q-rows per warp.
//    KV streamed in 64-row tiles. P round-trips through per-warp smem.
// ---------------------------------------------------------------------------
#define ATT_STRIDE 68
#define ATT_SMEM_FLOATS (64 * ATT_STRIDE * 2 + 128 * ATT_STRIDE)
#define ATT_SMEM_BYTES  (ATT_SMEM_FLOATS * 4)   // 69632

__global__ void __launch_bounds__(256) attn_mma()
{
    extern __shared__ float sm[];
    float* Ks = sm;                         // [64][68]
    float* Vs = sm + 64 * ATT_STRIDE;       // [64][68]
    float* Ps = sm + 2 * 64 * ATT_STRIDE;   // [128][68], first used as Qs

    const int tid  = threadIdx.x;
    const int wid  = tid >> 5;
    const int lane = tid & 31;
    const int g = lane >> 2, t = lane & 3;
    const int qb = blockIdx.x * 128;
    const int h  = blockIdx.y;
    const int b  = blockIdx.z;

    // --- load Q tile (scaled, tf32-rounded) into Ps region ---
    {
        const int row = tid >> 1;
        const int cb  = (tid & 1) * 32;
        const float* qp = &g_Q[((size_t)b * NN + qb + row) * DIMC + h * HD + cb];
        float* dst = &Ps[row * ATT_STRIDE + cb];
#pragma unroll
        for (int i = 0; i < 8; i++) {
            float4 v = *(const float4*)&qp[i * 4];
            dst[i * 4 + 0] = __uint_as_float(f2tf32(v.x * 0.125f));
            dst[i * 4 + 1] = __uint_as_float(f2tf32(v.y * 0.125f));
            dst[i * 4 + 2] = __uint_as_float(f2tf32(v.z * 0.125f));
            dst[i * 4 + 3] = __uint_as_float(f2tf32(v.w * 0.125f));
        }
    }
    __syncthreads();

    // --- Q fragments (8 ksteps over d=64) ---
    float* Pw = Ps + wid * 16 * ATT_STRIDE;
    uint32_t qf[8][4];
#pragma unroll
    for (int ks = 0; ks < 8; ks++) {
        const int kc = ks * 8 + t;
        qf[ks][0] = fbits(Pw[(g    ) * ATT_STRIDE + kc    ]);
        qf[ks][1] = fbits(Pw[(g + 8) * ATT_STRIDE + kc    ]);
        qf[ks][2] = fbits(Pw[(g    ) * ATT_STRIDE + kc + 4]);
        qf[ks][3] = fbits(Pw[(g + 8) * ATT_STRIDE + kc + 4]);
    }
    __syncthreads();

    float oacc[8][4];
#pragma unroll
    for (int nt = 0; nt < 8; nt++)
#pragma unroll
        for (int c = 0; c < 4; c++) oacc[nt][c] = 0.f;
    float m0r = -1e30f, m1r = -1e30f;
    float l0r = 0.f, l1r = 0.f;

    const float* kvb = &g_KV[(size_t)b * NP * 2 * DIMC + h * HD];

    for (int t0 = 0; t0 < NP; t0 += 64) {
        // --- load K,V tiles (tf32-rounded) ---
        {
            const int row = tid >> 2;           // 0..63
            const int cb  = (tid & 3) * 16;
            const float* kp = kvb + (size_t)(t0 + row) * (2 * DIMC) + cb;
            float* kd = &Ks[row * ATT_STRIDE + cb];
            float* vd = &Vs[row * ATT_STRIDE + cb];
#pragma unroll
            for (int i = 0; i < 4; i++) {
                float4 kv = *(const float4*)&kp[i * 4];
                float4 vv = *(const float4*)&kp[DIMC + i * 4];
                kd[i * 4 + 0] = __uint_as_float(f2tf32(kv.x));
                kd[i * 4 + 1] = __uint_as_float(f2tf32(kv.y));
                kd[i * 4 + 2] = __uint_as_float(f2tf32(kv.z));
                kd[i * 4 + 3] = __uint_as_float(f2tf32(kv.w));
                vd[i * 4 + 0] = __uint_as_float(f2tf32(vv.x));
                vd[i * 4 + 1] = __uint_as_float(f2tf32(vv.y));
                vd[i * 4 + 2] = __uint_as_float(f2tf32(vv.z));
                vd[i * 4 + 3] = __uint_as_float(f2tf32(vv.w));
            }
        }
        __syncthreads();

        // --- S = Q @ K^T ---
        float sacc[8][4];
#pragma unroll
        for (int nt = 0; nt < 8; nt++)
#pragma unroll
            for (int c = 0; c < 4; c++) sacc[nt][c] = 0.f;
#pragma unroll
        for (int ks = 0; ks < 8; ks++) {
            const int kc = ks * 8 + t;
#pragma unroll
            for (int nt = 0; nt < 8; nt++) {
                const int kr = (nt * 8 + g) * ATT_STRIDE;
                uint32_t b0 = fbits(Ks[kr + kc]);
                uint32_t b1 = fbits(Ks[kr + kc + 4]);
                mma1688(sacc[nt], qf[ks][0], qf[ks][1], qf[ks][2], qf[ks][3], b0, b1);
            }
        }

        // --- online softmax on fragments ---
        float mn0 = m0r, mn1 = m1r;
#pragma unroll
        for (int nt = 0; nt < 8; nt++) {
            mn0 = fmaxf(mn0, fmaxf(sacc[nt][0], sacc[nt][1]));
            mn1 = fmaxf(mn1, fmaxf(sacc[nt][2], sacc[nt][3]));
        }
        mn0 = fmaxf(mn0, __shfl_xor_sync(0xffffffffu, mn0, 1));
        mn0 = fmaxf(mn0, __shfl_xor_sync(0xffffffffu, mn0, 2));
        mn1 = fmaxf(mn1, __shfl_xor_sync(0xffffffffu, mn1, 1));
        mn1 = fmaxf(mn1, __shfl_xor_sync(0xffffffffu, mn1, 2));
        float corr0 = __expf(m0r - mn0);
        float corr1 = __expf(m1r - mn1);
        m0r = mn0; m1r = mn1;
        l0r *= corr0; l1r *= corr1;
#pragma unroll
        for (int nt = 0; nt < 8; nt++) {
            oacc[nt][0] *= corr0; oacc[nt][1] *= corr0;
            oacc[nt][2] *= corr1; oacc[nt][3] *= corr1;
        }
        float ps0 = 0.f, ps1 = 0.f;
#pragma unroll
        for (int nt = 0; nt < 8; nt++) {
            float p0 = __expf(sacc[nt][0] - mn0);
            float p1 = __expf(sacc[nt][1] - mn0);
            float p2 = __expf(sacc[nt][2] - mn1);
            float p3 = __expf(sacc[nt][3] - mn1);
            ps0 += p0 + p1; ps1 += p2 + p3;
            const int pc = nt * 8 + 2 * t;
            Pw[(g    ) * ATT_STRIDE + pc    ] = __uint_as_float(f2tf32(p0));
            Pw[(g    ) * ATT_STRIDE + pc + 1] = __uint_as_float(f2tf32(p1));
            Pw[(g + 8) * ATT_STRIDE + pc    ] = __uint_as_float(f2tf32(p2));
            Pw[(g + 8) * ATT_STRIDE + pc + 1] = __uint_as_float(f2tf32(p3));
        }
        l0r += ps0; l1r += ps1;
        __syncwarp();

        // --- O += P @ V ---
#pragma unroll
        for (int ks = 0; ks < 8; ks++) {
            const int kc = ks * 8 + t;
            uint32_t pa0 = fbits(Pw[(g    ) * ATT_STRIDE + kc    ]);
            uint32_t pa1 = fbits(Pw[(g + 8) * ATT_STRIDE + kc    ]);
            uint32_t pa2 = fbits(Pw[(g    ) * ATT_STRIDE + kc + 4]);
            uint32_t pa3 = fbits(Pw[(g + 8) * ATT_STRIDE + kc + 4]);
#pragma unroll
            for (int nt = 0; nt < 8; nt++) {
                const int vc = nt * 8 + g;
                uint32_t b0 = fbits(Vs[(kc    ) * ATT_STRIDE + vc]);
                uint32_t b1 = fbits(Vs[(kc + 4) * ATT_STRIDE + vc]);
                mma1688(oacc[nt], pa0, pa1, pa2, pa3, b0, b1);
            }
        }
        __syncthreads();
    }

    // final l reduction across quad
    l0r += __shfl_xor_sync(0xffffffffu, l0r, 1);
    l0r += __shfl_xor_sync(0xffffffffu, l0r, 2);
    l1r += __shfl_xor_sync(0xffffffffu, l1r, 1);
    l1r += __shfl_xor_sync(0xffffffffu, l1r, 2);
    const float inv0 = 1.f / l0r;
    const float inv1 = 1.f / l1r;

    const size_t orow0 = (size_t)b * NN + qb + wid * 16 + g;
#pragma unroll
    for (int nt = 0; nt < 8; nt++) {
        const int n = h * HD + nt * 8 + 2 * t;
        float2 v0 = make_float2(oacc[nt][0] * inv0, oacc[nt][1] * inv0);
        float2 v1 = make_float2(oacc[nt][2] * inv1, oacc[nt][3] * inv1);
        *(float2*)&g_O[orow0 * DIMC + n]       = v0;
        *(float2*)&g_O[(orow0 + 8) * DIMC + n] = v1;
    }
}

// ---------------------------------------------------------------------------
// Launch
// ---------------------------------------------------------------------------
extern "C" void kernel_launch(void* const* d_in, const int* in_sizes, int n_in,
                              void* d_out, int out_size)
{
    const float* x    = (const float*)d_in[0];
    const float* Wq   = (const float*)d_in[3];
    const float* Wkv  = (const float*)d_in[4];
    const float* Wsr  = (const float*)d_in[5];
    const float* bsr  = (const float*)d_in[6];
    const float* ln_g = (const float*)d_in[7];
    const float* ln_b = (const float*)d_in[8];
    const float* Wp   = (const float*)d_in[9];
    const float* bp   = (const float*)d_in[10];
    float* out = (float*)d_out;

    cudaFuncSetAttribute(attn_mma, cudaFuncAttributeMaxDynamicSharedMemorySize,
                         ATT_SMEM_BYTES);

    // 1) patches
    gather_patches<<<(BATCH * NP * DIMC + 255) / 256, 256>>>(x);

    // 2) SR conv as GEMM: Xsr = P @ Wsr_flat^T + bsr   [4096 x 512 x 2048]
    mma_gemm<<<dim3(DIMC / 128, BATCH * NP / 128), 256>>>(
        0, nullptr, Wsr, bsr, 1, nullptr, BATCH * NP, DIMC, KSR);

    // 3) LayerNorm in place
    ln_inplace<<<BATCH * NP, 128>>>(ln_g, ln_b);

    // 4) KV = Xn @ Wkv^T   [4096 x 1024 x 512]
    mma_gemm<<<dim3(2 * DIMC / 128, BATCH * NP / 128), 256>>>(
        1, nullptr, Wkv, nullptr, 2, nullptr, BATCH * NP, 2 * DIMC, DIMC);

    // 5) Q = x @ Wq^T   [16384 x 512 x 512]
    mma_gemm<<<dim3(DIMC / 128, BATCH * NN / 128), 256>>>(
        -1, x, Wq, nullptr, 3, nullptr, BATCH * NN, DIMC, DIMC);

    // 6) attention (tensor-core flash)
    attn_mma<<<dim3(NN / 128, NHEAD, BATCH), 256, ATT_SMEM_BYTES>>>();

    // 7) out = O @ Wp^T + bp   [16384 x 512 x 512]
    mma_gemm<<<dim3(DIMC / 128, BATCH * NN / 128), 256>>>(
        4, nullptr, Wp, bp, -1, out, BATCH * NN, DIMC, DIMC);
}

// round 5
// speedup vs baseline: 4.1259x; 1.4569x over previous
#include <cuda_runtime.h>
#include <cuda_fp16.h>
#include <cstdint>

// ---------------------------------------------------------------------------
// Problem constants (B=4, H=W=64, DIM=512, 8 heads, SR=2)
// ---------------------------------------------------------------------------
#define BATCH   4
#define HH      64
#define WW      64
#define NN      (HH * WW)        // 4096
#define DIMC    512
#define NHEAD   8
#define HD      (DIMC / NHEAD)   // 64
#define SRR     2
#define HP      (HH / SRR)       // 32
#define WP      (WW / SRR)       // 32
#define NP      (HP * WP)        // 1024
#define KSR     (DIMC * SRR * SRR) // 2048

// ---------------------------------------------------------------------------
// Scratch (device globals; no allocation anywhere)
// ---------------------------------------------------------------------------
__device__ float g_P  [(size_t)BATCH * NP * KSR];
__device__ float g_Xsr[(size_t)BATCH * NP * DIMC];
__device__ float g_KV [(size_t)BATCH * NP * 2 * DIMC];
__device__ float g_Q  [(size_t)BATCH * NN * DIMC];
__device__ float g_O  [(size_t)BATCH * NN * DIMC];

__device__ __forceinline__ float* pick_buf(int id) {
    switch (id) {
        case 0: return g_P;
        case 1: return g_Xsr;
        case 2: return g_KV;
        case 3: return g_Q;
        case 4: return g_O;
    }
    return nullptr;
}

// ---------------------------------------------------------------------------
// fp16 mma / ldmatrix helpers (sm_80+ PTX; fine on plain sm_100 target)
// ---------------------------------------------------------------------------
__device__ __forceinline__ uint32_t smem_u32(const void* p) {
    uint32_t a;
    asm("{ .reg .u64 t; cvta.to.shared.u64 t, %1; cvt.u32.u64 %0, t; }"
        : "=r"(a) : "l"(p));
    return a;
}

__device__ __forceinline__ uint32_t h2pack(float a, float b) {
    __half2 h = __floats2half2_rn(a, b);
    return *(uint32_t*)&h;
}

__device__ __forceinline__ void mma16816(float c[4],
                                         uint32_t a0, uint32_t a1,
                                         uint32_t a2, uint32_t a3,
                                         uint32_t b0, uint32_t b1) {
    asm volatile(
        "mma.sync.aligned.m16n8k16.row.col.f32.f16.f16.f32 "
        "{%0,%1,%2,%3}, {%4,%5,%6,%7}, {%8,%9}, {%0,%1,%2,%3};"
        : "+f"(c[0]), "+f"(c[1]), "+f"(c[2]), "+f"(c[3])
        : "r"(a0), "r"(a1), "r"(a2), "r"(a3), "r"(b0), "r"(b1));
}

__device__ __forceinline__ void ldmx4(uint32_t r[4], uint32_t addr) {
    asm volatile(
        "ldmatrix.sync.aligned.m8n8.x4.shared.b16 {%0,%1,%2,%3}, [%4];"
        : "=r"(r[0]), "=r"(r[1]), "=r"(r[2]), "=r"(r[3]) : "r"(addr));
}

__device__ __forceinline__ void ldmx4t(uint32_t r[4], uint32_t addr) {
    asm volatile(
        "ldmatrix.sync.aligned.m8n8.x4.trans.shared.b16 {%0,%1,%2,%3}, [%4];"
        : "=r"(r[0]), "=r"(r[1]), "=r"(r[2]), "=r"(r[3]) : "r"(addr));
}

// ---------------------------------------------------------------------------
// 1) Gather 2x2 patches: P[m, c*4 + ky*2 + kx]
// ---------------------------------------------------------------------------
__global__ void __launch_bounds__(256) gather_patches(const float* __restrict__ x) {
    int t = blockIdx.x * blockDim.x + threadIdx.x;
    if (t >= BATCH * NP * DIMC) return;
    int c  = t % DIMC;
    int m  = t / DIMC;
    int b  = m / NP;
    int np = m % NP;
    int i  = np / WP, j = np % WP;
    const float* xb = x + (size_t)b * NN * DIMC;
    float4 v;
    v.x = xb[((size_t)((2 * i + 0) * WW + 2 * j + 0)) * DIMC + c];
    v.y = xb[((size_t)((2 * i + 0) * WW + 2 * j + 1)) * DIMC + c];
    v.z = xb[((size_t)((2 * i + 1) * WW + 2 * j + 0)) * DIMC + c];
    v.w = xb[((size_t)((2 * i + 1) * WW + 2 * j + 1)) * DIMC + c];
    *(float4*)&g_P[(size_t)m * KSR + (size_t)c * 4] = v;
}

// ---------------------------------------------------------------------------
// 2) fp16 tensor-core GEMM: C[M,Nc] = A[M,K] @ W[Nc,K]^T (+bias)
//    128x128 CTA tile, BK=32, double-buffered smem, reg-prefetch pipeline,
//    ldmatrix fragment loads. fp32 accumulate.
// ---------------------------------------------------------------------------
#define GST 40  // smem row stride in halfs (conflict-free for ldmatrix)

__global__ void __launch_bounds__(256) hgemm(
    int Aid, const float* __restrict__ Aext,
    const float* __restrict__ Wt,
    const float* __restrict__ bias,
    int Cid, float* __restrict__ Cext,
    int M, int Nc, int K)
{
    const float* A = Aext ? Aext : pick_buf(Aid);
    float*       C = Cext ? Cext : pick_buf(Cid);

    __shared__ __align__(16) __half As[2][128][GST];
    __shared__ __align__(16) __half Bs[2][128][GST];

    const int tid  = threadIdx.x;
    const int wid  = tid >> 5;
    const int lane = tid & 31;
    const int g = lane >> 2, t = lane & 3;
    const int wm = (wid & 3) * 32;
    const int wn = (wid >> 2) * 64;
    const int m0 = blockIdx.y * 128;
    const int n0 = blockIdx.x * 128;

    float acc[2][8][4];
#pragma unroll
    for (int mt = 0; mt < 2; mt++)
#pragma unroll
        for (int nt = 0; nt < 8; nt++)
#pragma unroll
            for (int c = 0; c < 4; c++) acc[mt][nt][c] = 0.f;

    const int lrow = tid >> 1;          // 0..127
    const int lcb  = (tid & 1) * 16;    // 0 or 16 (halfs)
    const float* Ap = A  + (size_t)(m0 + lrow) * K + lcb;
    const float* Bp = Wt + (size_t)(n0 + lrow) * K + lcb;

    uint4 pa0, pa1, pb0, pb1;
    auto load_chunk = [&](int k0) {
        float4 a0 = *(const float4*)(Ap + k0);
        float4 a1 = *(const float4*)(Ap + k0 + 4);
        float4 a2 = *(const float4*)(Ap + k0 + 8);
        float4 a3 = *(const float4*)(Ap + k0 + 12);
        pa0 = make_uint4(h2pack(a0.x, a0.y), h2pack(a0.z, a0.w),
                         h2pack(a1.x, a1.y), h2pack(a1.z, a1.w));
        pa1 = make_uint4(h2pack(a2.x, a2.y), h2pack(a2.z, a2.w),
                         h2pack(a3.x, a3.y), h2pack(a3.z, a3.w));
        float4 b0 = *(const float4*)(Bp + k0);
        float4 b1 = *(const float4*)(Bp + k0 + 4);
        float4 b2 = *(const float4*)(Bp + k0 + 8);
        float4 b3 = *(const float4*)(Bp + k0 + 12);
        pb0 = make_uint4(h2pack(b0.x, b0.y), h2pack(b0.z, b0.w),
                         h2pack(b1.x, b1.y), h2pack(b1.z, b1.w));
        pb1 = make_uint4(h2pack(b2.x, b2.y), h2pack(b2.z, b2.w),
                         h2pack(b3.x, b3.y), h2pack(b3.z, b3.w));
    };

    const int nch = K >> 5;
    load_chunk(0);

    for (int kc = 0; kc < nch; kc++) {
        const int buf = kc & 1;
        *(uint4*)&As[buf][lrow][lcb]     = pa0;
        *(uint4*)&As[buf][lrow][lcb + 8] = pa1;
        *(uint4*)&Bs[buf][lrow][lcb]     = pb0;
        *(uint4*)&Bs[buf][lrow][lcb + 8] = pb1;
        __syncthreads();

        if (kc + 1 < nch) load_chunk((kc + 1) << 5);

#pragma unroll
        for (int ks = 0; ks < 2; ks++) {
            const int kcol = ks * 16;
            uint32_t af[2][4];
#pragma unroll
            for (int mt = 0; mt < 2; mt++)
                ldmx4(af[mt], smem_u32(&As[buf][wm + 16 * mt + (lane & 15)]
                                          [kcol + ((lane >> 4) << 3)]));
            uint32_t bf[4][4];
#pragma unroll
            for (int bp = 0; bp < 4; bp++)
                ldmx4(bf[bp], smem_u32(&Bs[buf][wn + 16 * bp + ((lane >> 4) << 3) + (lane & 7)]
                                          [kcol + ((lane >> 3) & 1) * 8]));
#pragma unroll
            for (int nt = 0; nt < 8; nt++) {
                uint32_t b0 = bf[nt >> 1][(nt & 1) * 2];
                uint32_t b1 = bf[nt >> 1][(nt & 1) * 2 + 1];
                mma16816(acc[0][nt], af[0][0], af[0][1], af[0][2], af[0][3], b0, b1);
                mma16816(acc[1][nt], af[1][0], af[1][1], af[1][2], af[1][3], b0, b1);
            }
        }
        __syncthreads();
    }

    // epilogue (fp32)
#pragma unroll
    for (int mt = 0; mt < 2; mt++) {
        const int mr = m0 + wm + mt * 16 + g;
#pragma unroll
        for (int nt = 0; nt < 8; nt++) {
            const int n = n0 + wn + nt * 8 + 2 * t;
            float bx = 0.f, by = 0.f;
            if (bias) { bx = bias[n]; by = bias[n + 1]; }
            float2 v0 = make_float2(acc[mt][nt][0] + bx, acc[mt][nt][1] + by);
            float2 v1 = make_float2(acc[mt][nt][2] + bx, acc[mt][nt][3] + by);
            *(float2*)&C[(size_t)mr * Nc + n]       = v0;
            *(float2*)&C[(size_t)(mr + 8) * Nc + n] = v1;
        }
    }
}

// ---------------------------------------------------------------------------
// 3) LayerNorm in-place on g_Xsr rows (512 wide)
// ---------------------------------------------------------------------------
__global__ void __launch_bounds__(128) ln_inplace(const float* __restrict__ gam,
                                                  const float* __restrict__ bet)
{
    float* p = g_Xsr + (size_t)blockIdx.x * DIMC;
    int tid = threadIdx.x;
    float v[4];
    float s = 0.f, sq = 0.f;
#pragma unroll
    for (int i = 0; i < 4; i++) {
        v[i] = p[tid + i * 128];
        s += v[i];
        sq += v[i] * v[i];
    }
#pragma unroll
    for (int o = 16; o > 0; o >>= 1) {
        s  += __shfl_xor_sync(0xffffffffu, s,  o);
        sq += __shfl_xor_sync(0xffffffffu, sq, o);
    }
    __shared__ float ss[4], sqs[4];
    int wid = tid >> 5, lid = tid & 31;
    if (lid == 0) { ss[wid] = s; sqs[wid] = sq; }
    __syncthreads();
    s  = ss[0] + ss[1] + ss[2] + ss[3];
    sq = sqs[0] + sqs[1] + sqs[2] + sqs[3];
    float mu  = s * (1.f / DIMC);
    float var = sq * (1.f / DIMC) - mu * mu;
    float inv = rsqrtf(var + 1e-5f);
#pragma unroll
    for (int i = 0; i < 4; i++) {
        int c = tid + i * 128;
        p[c] = (v[i] - mu) * inv * gam[c] + bet[c];
    }
}

// ---------------------------------------------------------------------------
// 4) Flash attention, fp16 mma (m16n8k16), P stays in registers.
//    Grid (NN/128, NHEAD, BATCH), 256 threads, 16 q-rows/warp, KV tile 64.
// ---------------------------------------------------------------------------
#define AST 72  // attention smem row stride in halfs

__global__ void __launch_bounds__(256) attn_h()
{
    __shared__ __align__(16) __half Qs[128][AST];
    __shared__ __align__(16) __half Ks[64][AST];
    __shared__ __align__(16) __half Vs[64][AST];

    const int tid  = threadIdx.x;
    const int wid  = tid >> 5;
    const int lane = tid & 31;
    const int g = lane >> 2, t = lane & 3;
    const int qb = blockIdx.x * 128;
    const int h  = blockIdx.y;
    const int b  = blockIdx.z;

    // --- Q tile: fp32 load, scale, fp16 store ---
    {
        const int row = tid >> 1;
        const int cb  = (tid & 1) * 32;
        const float* qp = &g_Q[((size_t)b * NN + qb + row) * DIMC + h * HD + cb];
        uint32_t hx[16];
#pragma unroll
        for (int i = 0; i < 8; i++) {
            float4 v = *(const float4*)&qp[i * 4];
            hx[i * 2]     = h2pack(v.x * 0.125f, v.y * 0.125f);
            hx[i * 2 + 1] = h2pack(v.z * 0.125f, v.w * 0.125f);
        }
#pragma unroll
        for (int i = 0; i < 4; i++)
            *(uint4*)&Qs[row][cb + i * 8] =
                make_uint4(hx[i * 4], hx[i * 4 + 1], hx[i * 4 + 2], hx[i * 4 + 3]);
    }
    __syncthreads();

    // --- Q fragments: 4 ksteps over d=64 ---
    const int wq = wid * 16;
    uint32_t qf[4][4];
#pragma unroll
    for (int ks = 0; ks < 4; ks++)
        ldmx4(qf[ks], smem_u32(&Qs[wq + (lane & 15)][ks * 16 + ((lane >> 4) << 3)]));

    float oacc[8][4];
#pragma unroll
    for (int dt = 0; dt < 8; dt++)
#pragma unroll
        for (int c = 0; c < 4; c++) oacc[dt][c] = 0.f;
    float m0r = -1e30f, m1r = -1e30f, l0r = 0.f, l1r = 0.f;

    const float* kvb = &g_KV[(size_t)b * NP * 2 * DIMC + h * HD];
    const int krow = tid >> 2;          // 0..63
    const int kcb  = (tid & 3) * 16;    // 0,16,32,48

    uint4 kp0, kp1, vp0, vp1;
    auto load_kv = [&](int t0) {
        const float* kp = kvb + (size_t)(t0 + krow) * (2 * DIMC) + kcb;
        float4 k0 = *(const float4*)(kp);
        float4 k1 = *(const float4*)(kp + 4);
        float4 k2 = *(const float4*)(kp + 8);
        float4 k3 = *(const float4*)(kp + 12);
        kp0 = make_uint4(h2pack(k0.x, k0.y), h2pack(k0.z, k0.w),
                         h2pack(k1.x, k1.y), h2pack(k1.z, k1.w));
        kp1 = make_uint4(h2pack(k2.x, k2.y), h2pack(k2.z, k2.w),
                         h2pack(k3.x, k3.y), h2pack(k3.z, k3.w));
        float4 v0 = *(const float4*)(kp + DIMC);
        float4 v1 = *(const float4*)(kp + DIMC + 4);
        float4 v2 = *(const float4*)(kp + DIMC + 8);
        float4 v3 = *(const float4*)(kp + DIMC + 12);
        vp0 = make_uint4(h2pack(v0.x, v0.y), h2pack(v0.z, v0.w),
                         h2pack(v1.x, v1.y), h2pack(v1.z, v1.w));
        vp1 = make_uint4(h2pack(v2.x, v2.y), h2pack(v2.z, v2.w),
                         h2pack(v3.x, v3.y), h2pack(v3.z, v3.w));
    };

    load_kv(0);

    for (int t0 = 0; t0 < NP; t0 += 64) {
        *(uint4*)&Ks[krow][kcb]     = kp0;
        *(uint4*)&Ks[krow][kcb + 8] = kp1;
        *(uint4*)&Vs[krow][kcb]     = vp0;
        *(uint4*)&Vs[krow][kcb + 8] = vp1;
        __syncthreads();

        if (t0 + 64 < NP) load_kv(t0 + 64);

        // --- S = Q @ K^T  (8 kv n-tiles, 4 d ksteps) ---
        float sacc[8][4];
#pragma unroll
        for (int nt = 0; nt < 8; nt++)
#pragma unroll
            for (int c = 0; c < 4; c++) sacc[nt][c] = 0.f;
#pragma unroll
        for (int ks = 0; ks < 4; ks++) {
            uint32_t bf[4][4];
#pragma unroll
            for (int bp = 0; bp < 4; bp++)
                ldmx4(bf[bp], smem_u32(&Ks[16 * bp + ((lane >> 4) << 3) + (lane & 7)]
                                          [ks * 16 + ((lane >> 3) & 1) * 8]));
#pragma unroll
            for (int nt = 0; nt < 8; nt++)
                mma16816(sacc[nt], qf[ks][0], qf[ks][1], qf[ks][2], qf[ks][3],
                         bf[nt >> 1][(nt & 1) * 2], bf[nt >> 1][(nt & 1) * 2 + 1]);
        }

        // --- online softmax on fragments ---
        float mn0 = m0r, mn1 = m1r;
#pragma unroll
        for (int nt = 0; nt < 8; nt++) {
            mn0 = fmaxf(mn0, fmaxf(sacc[nt][0], sacc[nt][1]));
            mn1 = fmaxf(mn1, fmaxf(sacc[nt][2], sacc[nt][3]));
        }
        mn0 = fmaxf(mn0, __shfl_xor_sync(0xffffffffu, mn0, 1));
        mn0 = fmaxf(mn0, __shfl_xor_sync(0xffffffffu, mn0, 2));
        mn1 = fmaxf(mn1, __shfl_xor_sync(0xffffffffu, mn1, 1));
        mn1 = fmaxf(mn1, __shfl_xor_sync(0xffffffffu, mn1, 2));
        float corr0 = __expf(m0r - mn0);
        float corr1 = __expf(m1r - mn1);
        m0r = mn0; m1r = mn1;
        l0r *= corr0; l1r *= corr1;
#pragma unroll
        for (int dt = 0; dt < 8; dt++) {
            oacc[dt][0] *= corr0; oacc[dt][1] *= corr0;
            oacc[dt][2] *= corr1; oacc[dt][3] *= corr1;
        }
        float ps0 = 0.f, ps1 = 0.f;
#pragma unroll
        for (int nt = 0; nt < 8; nt++) {
            sacc[nt][0] = __expf(sacc[nt][0] - mn0);
            sacc[nt][1] = __expf(sacc[nt][1] - mn0);
            sacc[nt][2] = __expf(sacc[nt][2] - mn1);
            sacc[nt][3] = __expf(sacc[nt][3] - mn1);
            ps0 += sacc[nt][0] + sacc[nt][1];
            ps1 += sacc[nt][2] + sacc[nt][3];
        }
        l0r += ps0; l1r += ps1;

        // --- pack P to fp16 A-fragments (C-layout == A-layout trick) ---
        uint32_t pk[4][4];
#pragma unroll
        for (int ks = 0; ks < 4; ks++) {
            pk[ks][0] = h2pack(sacc[2 * ks][0],     sacc[2 * ks][1]);
            pk[ks][1] = h2pack(sacc[2 * ks][2],     sacc[2 * ks][3]);
            pk[ks][2] = h2pack(sacc[2 * ks + 1][0], sacc[2 * ks + 1][1]);
            pk[ks][3] = h2pack(sacc[2 * ks + 1][2], sacc[2 * ks + 1][3]);
        }

        // --- O += P @ V  (trans ldmatrix on natural-layout V) ---
#pragma unroll
        for (int ks = 0; ks < 4; ks++) {
            uint32_t vf[4][4];
#pragma unroll
            for (int dp = 0; dp < 4; dp++)
                ldmx4t(vf[dp], smem_u32(&Vs[16 * ks + ((lane >> 3) & 1) * 8 + (lane & 7)]
                                           [16 * dp + ((lane >> 4) << 3)]));
#pragma unroll
            for (int dt = 0; dt < 8; dt++)
                mma16816(oacc[dt], pk[ks][0], pk[ks][1], pk[ks][2], pk[ks][3],
                         vf[dt >> 1][(dt & 1) * 2], vf[dt >> 1][(dt & 1) * 2 + 1]);
        }
        __syncthreads();
    }

    l0r += __shfl_xor_sync(0xffffffffu, l0r, 1);
    l0r += __shfl_xor_sync(0xffffffffu, l0r, 2);
    l1r += __shfl_xor_sync(0xffffffffu, l1r, 1);
    l1r += __shfl_xor_sync(0xffffffffu, l1r, 2);
    const float inv0 = 1.f / l0r;
    const float inv1 = 1.f / l1r;

    const size_t orow0 = (size_t)b * NN + qb + wq + g;
#pragma unroll
    for (int dt = 0; dt < 8; dt++) {
        const int n = h * HD + dt * 8 + 2 * t;
        float2 v0 = make_float2(oacc[dt][0] * inv0, oacc[dt][1] * inv0);
        float2 v1 = make_float2(oacc[dt][2] * inv1, oacc[dt][3] * inv1);
        *(float2*)&g_O[orow0 * DIMC + n]       = v0;
        *(float2*)&g_O[(orow0 + 8) * DIMC + n] = v1;
    }
}

// ---------------------------------------------------------------------------
// Launch
// ---------------------------------------------------------------------------
extern "C" void kernel_launch(void* const* d_in, const int* in_sizes, int n_in,
                              void* d_out, int out_size)
{
    const float* x    = (const float*)d_in[0];
    const float* Wq   = (const float*)d_in[3];
    const float* Wkv  = (const float*)d_in[4];
    const float* Wsr  = (const float*)d_in[5];
    const float* bsr  = (const float*)d_in[6];
    const float* ln_g = (const float*)d_in[7];
    const float* ln_b = (const float*)d_in[8];
    const float* Wp   = (const float*)d_in[9];
    const float* bp   = (const float*)d_in[10];
    float* out = (float*)d_out;

    // 1) patches
    gather_patches<<<(BATCH * NP * DIMC + 255) / 256, 256>>>(x);

    // 2) SR conv as GEMM: Xsr = P @ Wsr_flat^T + bsr   [4096 x 512 x 2048]
    hgemm<<<dim3(DIMC / 128, BATCH * NP / 128), 256>>>(
        0, nullptr, Wsr, bsr, 1, nullptr, BATCH * NP, DIMC, KSR);

    // 3) LayerNorm in place
    ln_inplace<<<BATCH * NP, 128>>>(ln_g, ln_b);

    // 4) KV = Xn @ Wkv^T   [4096 x 1024 x 512]
    hgemm<<<dim3(2 * DIMC / 128, BATCH * NP / 128), 256>>>(
        1, nullptr, Wkv, nullptr, 2, nullptr, BATCH * NP, 2 * DIMC, DIMC);

    // 5) Q = x @ Wq^T   [16384 x 512 x 512]
    hgemm<<<dim3(DIMC / 128, BATCH * NN / 128), 256>>>(
        -1, x, Wq, nullptr, 3, nullptr, BATCH * NN, DIMC, DIMC);

    // 6) attention (fp16 tensor-core flash, register-resident P)
    attn_h<<<dim3(NN / 128, NHEAD, BATCH), 256>>>();

    // 7) out = O @ Wp^T + bp   [16384 x 512 x 512]
    hgemm<<<dim3(DIMC / 128, BATCH * NN / 128), 256>>>(
        4, nullptr, Wp, bp, -1, out, BATCH * NN, DIMC, DIMC);
}

// round 6
// speedup vs baseline: 7.1023x; 1.7214x over previous
#include <cuda_runtime.h>
#include <cuda_fp16.h>
#include <cstdint>

// ---------------------------------------------------------------------------
// Problem constants (B=4, H=W=64, DIM=512, 8 heads, SR=2)
// ---------------------------------------------------------------------------
#define BATCH   4
#define HH      64
#define WW      64
#define NN      (HH * WW)        // 4096
#define DIMC    512
#define NHEAD   8
#define HD      (DIMC / NHEAD)   // 64
#define SRR     2
#define HP      (HH / SRR)       // 32
#define WP      (WW / SRR)       // 32
#define NP      (HP * WP)        // 1024
#define KSR     (DIMC * SRR * SRR) // 2048

// ---------------------------------------------------------------------------
// Scratch (device globals; fp16 for everything that crosses kernels)
// ---------------------------------------------------------------------------
__device__ __half g_Ph  [(size_t)BATCH * NP * KSR];      // 16 MB patches
__device__ __half g_xh  [(size_t)BATCH * NN * DIMC];     // 16 MB x in fp16
__device__ float  g_Xsr [(size_t)BATCH * NP * DIMC];     //  8 MB conv out (fp32 for LN)
__device__ __half g_Xnh [(size_t)BATCH * NP * DIMC];     //  4 MB LN out
__device__ __half g_KVh [(size_t)BATCH * NP * 2 * DIMC]; //  8 MB kv
__device__ __half g_Qh  [(size_t)BATCH * NN * DIMC];     // 16 MB q (pre-scaled)
__device__ __half g_Oh  [(size_t)BATCH * NN * DIMC];     // 16 MB attention out
__device__ __half g_Wsrh[(size_t)DIMC * KSR];
__device__ __half g_Wkvh[(size_t)2 * DIMC * DIMC];
__device__ __half g_Wqh [(size_t)DIMC * DIMC];
__device__ __half g_Wph [(size_t)DIMC * DIMC];

__device__ __forceinline__ __half* pick_h(int id) {
    switch (id) {
        case 0: return g_Ph;
        case 1: return g_xh;
        case 2: return g_Xnh;
        case 3: return g_KVh;
        case 4: return g_Qh;
        case 5: return g_Oh;
        case 6: return g_Wsrh;
        case 7: return g_Wkvh;
        case 8: return g_Wqh;
        case 9: return g_Wph;
    }
    return nullptr;
}

// ---------------------------------------------------------------------------
// PTX helpers
// ---------------------------------------------------------------------------
__device__ __forceinline__ uint32_t smem_u32(const void* p) {
    uint32_t a;
    asm("{ .reg .u64 t; cvta.to.shared.u64 t, %1; cvt.u32.u64 %0, t; }"
        : "=r"(a) : "l"(p));
    return a;
}
__device__ __forceinline__ uint32_t h2pack(float a, float b) {
    __half2 h = __floats2half2_rn(a, b);
    return *(uint32_t*)&h;
}
__device__ __forceinline__ void mma16816(float c[4],
                                         uint32_t a0, uint32_t a1,
                                         uint32_t a2, uint32_t a3,
                                         uint32_t b0, uint32_t b1) {
    asm volatile(
        "mma.sync.aligned.m16n8k16.row.col.f32.f16.f16.f32 "
        "{%0,%1,%2,%3}, {%4,%5,%6,%7}, {%8,%9}, {%0,%1,%2,%3};"
        : "+f"(c[0]), "+f"(c[1]), "+f"(c[2]), "+f"(c[3])
        : "r"(a0), "r"(a1), "r"(a2), "r"(a3), "r"(b0), "r"(b1));
}
__device__ __forceinline__ void ldmx4(uint32_t r[4], uint32_t addr) {
    asm volatile(
        "ldmatrix.sync.aligned.m8n8.x4.shared.b16 {%0,%1,%2,%3}, [%4];"
        : "=r"(r[0]), "=r"(r[1]), "=r"(r[2]), "=r"(r[3]) : "r"(addr));
}
__device__ __forceinline__ void ldmx4t(uint32_t r[4], uint32_t addr) {
    asm volatile(
        "ldmatrix.sync.aligned.m8n8.x4.trans.shared.b16 {%0,%1,%2,%3}, [%4];"
        : "=r"(r[0]), "=r"(r[1]), "=r"(r[2]), "=r"(r[3]) : "r"(addr));
}
#define CP_ASYNC16(saddr, gptr) \
    asm volatile("cp.async.cg.shared.global [%0], [%1], 16;" \
        :: "r"(saddr), "l"(gptr))
#define CP_COMMIT() asm volatile("cp.async.commit_group;" ::: "memory")
#define CP_WAIT(N)  asm volatile("cp.async.wait_group %0;" :: "n"(N) : "memory")

// ---------------------------------------------------------------------------
// 0) fp32 -> fp16 convert (vectorized)
// ---------------------------------------------------------------------------
__global__ void __launch_bounds__(256) f2h(const float* __restrict__ src,
                                           int dstId, int n) {
    __half* dst = pick_h(dstId);
    int i = (blockIdx.x * blockDim.x + threadIdx.x) * 4;
    if (i >= n) return;
    float4 v = *(const float4*)&src[i];
    *(uint2*)&dst[i] = make_uint2(h2pack(v.x, v.y), h2pack(v.z, v.w));
}

// ---------------------------------------------------------------------------
// 1) Gather 2x2 patches -> fp16: Ph[m, c*4 + ky*2 + kx]
// ---------------------------------------------------------------------------
__global__ void __launch_bounds__(256) gather_patches(const float* __restrict__ x) {
    int t = blockIdx.x * blockDim.x + threadIdx.x;
    if (t >= BATCH * NP * DIMC) return;
    int c  = t % DIMC;
    int m  = t / DIMC;
    int b  = m / NP;
    int np = m % NP;
    int i  = np / WP, j = np % WP;
    const float* xb = x + (size_t)b * NN * DIMC;
    float v0 = xb[((size_t)((2 * i + 0) * WW + 2 * j + 0)) * DIMC + c];
    float v1 = xb[((size_t)((2 * i + 0) * WW + 2 * j + 1)) * DIMC + c];
    float v2 = xb[((size_t)((2 * i + 1) * WW + 2 * j + 0)) * DIMC + c];
    float v3 = xb[((size_t)((2 * i + 1) * WW + 2 * j + 1)) * DIMC + c];
    *(uint2*)&g_Ph[(size_t)m * KSR + (size_t)c * 4] =
        make_uint2(h2pack(v0, v1), h2pack(v2, v3));
}

// ---------------------------------------------------------------------------
// 2) fp16 GEMM with cp.async: C[M,Nc] = scale*(A[M,K] @ W[Nc,K]^T) + bias
//    128x128 CTA tile, BK=32, double-buffered cp.async, ldmatrix, fp32 accum.
// ---------------------------------------------------------------------------
#define GST 40

__global__ void __launch_bounds__(256) hgemm(
    int Aid, int Wid, const float* __restrict__ bias, float scale,
    int Cfp16, int Cid, float* __restrict__ Cext,
    int M, int Nc, int K)
{
    const __half* A = pick_h(Aid);
    const __half* W = pick_h(Wid);

    __shared__ __align__(16) __half As[2][128][GST];
    __shared__ __align__(16) __half Bs[2][128][GST];

    const int tid  = threadIdx.x;
    const int wid  = tid >> 5;
    const int lane = tid & 31;
    const int g = lane >> 2, t = lane & 3;
    const int wm = (wid & 3) * 32;
    const int wn = (wid >> 2) * 64;
    const int m0 = blockIdx.y * 128;
    const int n0 = blockIdx.x * 128;

    float acc[2][8][4];
#pragma unroll
    for (int mt = 0; mt < 2; mt++)
#pragma unroll
        for (int nt = 0; nt < 8; nt++)
#pragma unroll
            for (int c = 0; c < 4; c++) acc[mt][nt][c] = 0.f;

    auto issue = [&](int kc) {
        const int k0 = kc << 5;
        const int buf = kc & 1;
#pragma unroll
        for (int j = 0; j < 2; j++) {
            int id = tid + j * 256;          // 0..511
            int r  = id >> 2;                // row 0..127
            int c8 = (id & 3) * 8;           // half col 0,8,16,24
            CP_ASYNC16(smem_u32(&As[buf][r][c8]),
                       A + (size_t)(m0 + r) * K + k0 + c8);
            CP_ASYNC16(smem_u32(&Bs[buf][r][c8]),
                       W + (size_t)(n0 + r) * K + k0 + c8);
        }
        CP_COMMIT();
    };

    const int nch = K >> 5;
    issue(0);

    for (int kc = 0; kc < nch; kc++) {
        const int buf = kc & 1;
        if (kc + 1 < nch) { issue(kc + 1); CP_WAIT(1); }
        else              { CP_WAIT(0); }
        __syncthreads();

#pragma unroll
        for (int ks = 0; ks < 2; ks++) {
            const int kcol = ks * 16;
            uint32_t af[2][4];
#pragma unroll
            for (int mt = 0; mt < 2; mt++)
                ldmx4(af[mt], smem_u32(&As[buf][wm + 16 * mt + (lane & 15)]
                                          [kcol + ((lane >> 4) << 3)]));
            uint32_t bf[4][4];
#pragma unroll
            for (int bp = 0; bp < 4; bp++)
                ldmx4(bf[bp], smem_u32(&Bs[buf][wn + 16 * bp + ((lane >> 4) << 3) + (lane & 7)]
                                          [kcol + ((lane >> 3) & 1) * 8]));
#pragma unroll
            for (int nt = 0; nt < 8; nt++) {
                uint32_t b0 = bf[nt >> 1][(nt & 1) * 2];
                uint32_t b1 = bf[nt >> 1][(nt & 1) * 2 + 1];
                mma16816(acc[0][nt], af[0][0], af[0][1], af[0][2], af[0][3], b0, b1);
                mma16816(acc[1][nt], af[1][0], af[1][1], af[1][2], af[1][3], b0, b1);
            }
        }
        __syncthreads();
    }

    // epilogue
    __half* Ch = Cfp16 ? pick_h(Cid) : nullptr;
    float*  Cf = Cfp16 ? nullptr : (Cext ? Cext : g_Xsr);
#pragma unroll
    for (int mt = 0; mt < 2; mt++) {
        const int mr = m0 + wm + mt * 16 + g;
#pragma unroll
        for (int nt = 0; nt < 8; nt++) {
            const int n = n0 + wn + nt * 8 + 2 * t;
            float bx = 0.f, by = 0.f;
            if (bias) { bx = bias[n]; by = bias[n + 1]; }
            float v00 = acc[mt][nt][0] * scale + bx;
            float v01 = acc[mt][nt][1] * scale + by;
            float v10 = acc[mt][nt][2] * scale + bx;
            float v11 = acc[mt][nt][3] * scale + by;
            if (Cfp16) {
                *(uint32_t*)&Ch[(size_t)mr * Nc + n]       = h2pack(v00, v01);
                *(uint32_t*)&Ch[(size_t)(mr + 8) * Nc + n] = h2pack(v10, v11);
            } else {
                *(float2*)&Cf[(size_t)mr * Nc + n]       = make_float2(v00, v01);
                *(float2*)&Cf[(size_t)(mr + 8) * Nc + n] = make_float2(v10, v11);
            }
        }
    }
}

// ---------------------------------------------------------------------------
// 3) LayerNorm: g_Xsr (fp32) -> g_Xnh (fp16). One block of 128 per row.
// ---------------------------------------------------------------------------
__global__ void __launch_bounds__(128) ln_rows(const float* __restrict__ gam,
                                               const float* __restrict__ bet)
{
    const float* p = g_Xsr + (size_t)blockIdx.x * DIMC;
    __half* o = g_Xnh + (size_t)blockIdx.x * DIMC;
    int tid = threadIdx.x;
    float4 v = *(const float4*)&p[tid * 4];
    float s  = v.x + v.y + v.z + v.w;
    float sq = v.x * v.x + v.y * v.y + v.z * v.z + v.w * v.w;
#pragma unroll
    for (int off = 16; off > 0; off >>= 1) {
        s  += __shfl_xor_sync(0xffffffffu, s,  off);
        sq += __shfl_xor_sync(0xffffffffu, sq, off);
    }
    __shared__ float ss[4], sqs[4];
    int wid = tid >> 5, lid = tid & 31;
    if (lid == 0) { ss[wid] = s; sqs[wid] = sq; }
    __syncthreads();
    s  = ss[0] + ss[1] + ss[2] + ss[3];
    sq = sqs[0] + sqs[1] + sqs[2] + sqs[3];
    float mu  = s * (1.f / DIMC);
    float var = sq * (1.f / DIMC) - mu * mu;
    float inv = rsqrtf(var + 1e-5f);
    int c = tid * 4;
    float4 gm = *(const float4*)&gam[c];
    float4 bt = *(const float4*)&bet[c];
    float r0 = (v.x - mu) * inv * gm.x + bt.x;
    float r1 = (v.y - mu) * inv * gm.y + bt.y;
    float r2 = (v.z - mu) * inv * gm.z + bt.z;
    float r3 = (v.w - mu) * inv * gm.w + bt.w;
    *(uint2*)&o[c] = make_uint2(h2pack(r0, r1), h2pack(r2, r3));
}

// ---------------------------------------------------------------------------
// 4) Flash attention, fp16 mma, cp.async double-buffered K/V, reg-resident P.
//    Grid (NN/128, NHEAD, BATCH), 256 threads. Q pre-scaled in g_Qh.
// ---------------------------------------------------------------------------
#define AST 72
#define ATT_SMEM_BYTES ((128 * AST + 2 * 64 * AST * 2) * 2)  // 55296

__global__ void __launch_bounds__(256) attn_h()
{
    extern __shared__ __align__(16) __half smh[];
    __half* Qs = smh;                       // [128][AST]
    __half* Ks = Qs + 128 * AST;            // [2][64][AST]
    __half* Vs = Ks + 2 * 64 * AST;         // [2][64][AST]

    const int tid  = threadIdx.x;
    const int wid  = tid >> 5;
    const int lane = tid & 31;
    const int g = lane >> 2, t = lane & 3;
    const int qb = blockIdx.x * 128;
    const int h  = blockIdx.y;
    const int b  = blockIdx.z;

    const __half* qbase = g_Qh + ((size_t)b * NN + qb) * DIMC + h * HD;
    const __half* kvb   = g_KVh + (size_t)b * NP * 2 * DIMC + h * HD;

    // --- Q tile via cp.async (group 0) ---
#pragma unroll
    for (int j = 0; j < 4; j++) {
        int id = tid + j * 256;             // 0..1023
        int r  = id >> 3;                   // 0..127
        int c8 = (id & 7) * 8;
        CP_ASYNC16(smem_u32(&Qs[r * AST + c8]), qbase + (size_t)r * DIMC + c8);
    }
    CP_COMMIT();

    auto issue_kv = [&](int t0, int buf) {
#pragma unroll
        for (int j = 0; j < 2; j++) {
            int id = tid + j * 256;         // 0..511
            int r  = id >> 3;               // 0..63
            int c8 = (id & 7) * 8;
            const __half* src = kvb + (size_t)(t0 + r) * (2 * DIMC) + c8;
            CP_ASYNC16(smem_u32(&Ks[(buf * 64 + r) * AST + c8]), src);
            CP_ASYNC16(smem_u32(&Vs[(buf * 64 + r) * AST + c8]), src + DIMC);
        }
        CP_COMMIT();
    };

    issue_kv(0, 0);      // group 1
    CP_WAIT(1);          // Q (group 0) complete
    __syncthreads();

    // --- Q fragments ---
    const int wq = wid * 16;
    uint32_t qf[4][4];
#pragma unroll
    for (int ks = 0; ks < 4; ks++)
        ldmx4(qf[ks], smem_u32(&Qs[(wq + (lane & 15)) * AST
                                   + ks * 16 + ((lane >> 4) << 3)]));

    float oacc[8][4];
#pragma unroll
    for (int dt = 0; dt < 8; dt++)
#pragma unroll
        for (int c = 0; c < 4; c++) oacc[dt][c] = 0.f;
    float m0r = -1e30f, m1r = -1e30f, l0r = 0.f, l1r = 0.f;

    const int niter = NP / 64;
    for (int it = 0; it < niter; it++) {
        const int buf = it & 1;
        if (it + 1 < niter) { issue_kv((it + 1) * 64, (it + 1) & 1); CP_WAIT(1); }
        else                { CP_WAIT(0); }
        __syncthreads();

        const __half* Kb = Ks + buf * 64 * AST;
        const __half* Vb = Vs + buf * 64 * AST;

        // --- S = Q @ K^T ---
        float sacc[8][4];
#pragma unroll
        for (int nt = 0; nt < 8; nt++)
#pragma unroll
            for (int c = 0; c < 4; c++) sacc[nt][c] = 0.f;
#pragma unroll
        for (int ks = 0; ks < 4; ks++) {
            uint32_t bf[4][4];
#pragma unroll
            for (int bp = 0; bp < 4; bp++)
                ldmx4(bf[bp], smem_u32(&Kb[(16 * bp + ((lane >> 4) << 3) + (lane & 7)) * AST
                                           + ks * 16 + ((lane >> 3) & 1) * 8]));
#pragma unroll
            for (int nt = 0; nt < 8; nt++)
                mma16816(sacc[nt], qf[ks][0], qf[ks][1], qf[ks][2], qf[ks][3],
                         bf[nt >> 1][(nt & 1) * 2], bf[nt >> 1][(nt & 1) * 2 + 1]);
        }

        // --- online softmax ---
        float mn0 = m0r, mn1 = m1r;
#pragma unroll
        for (int nt = 0; nt < 8; nt++) {
            mn0 = fmaxf(mn0, fmaxf(sacc[nt][0], sacc[nt][1]));
            mn1 = fmaxf(mn1, fmaxf(sacc[nt][2], sacc[nt][3]));
        }
        mn0 = fmaxf(mn0, __shfl_xor_sync(0xffffffffu, mn0, 1));
        mn0 = fmaxf(mn0, __shfl_xor_sync(0xffffffffu, mn0, 2));
        mn1 = fmaxf(mn1, __shfl_xor_sync(0xffffffffu, mn1, 1));
        mn1 = fmaxf(mn1, __shfl_xor_sync(0xffffffffu, mn1, 2));
        float corr0 = __expf(m0r - mn0);
        float corr1 = __expf(m1r - mn1);
        m0r = mn0; m1r = mn1;
        l0r *= corr0; l1r *= corr1;
#pragma unroll
        for (int dt = 0; dt < 8; dt++) {
            oacc[dt][0] *= corr0; oacc[dt][1] *= corr0;
            oacc[dt][2] *= corr1; oacc[dt][3] *= corr1;
        }
        float ps0 = 0.f, ps1 = 0.f;
#pragma unroll
        for (int nt = 0; nt < 8; nt++) {
            sacc[nt][0] = __expf(sacc[nt][0] - mn0);
            sacc[nt][1] = __expf(sacc[nt][1] - mn0);
            sacc[nt][2] = __expf(sacc[nt][2] - mn1);
            sacc[nt][3] = __expf(sacc[nt][3] - mn1);
            ps0 += sacc[nt][0] + sacc[nt][1];
            ps1 += sacc[nt][2] + sacc[nt][3];
        }
        l0r += ps0; l1r += ps1;

        // --- pack P (C-layout == A-layout trick) ---
        uint32_t pk[4][4];
#pragma unroll
        for (int ks = 0; ks < 4; ks++) {
            pk[ks][0] = h2pack(sacc[2 * ks][0],     sacc[2 * ks][1]);
            pk[ks][1] = h2pack(sacc[2 * ks][2],     sacc[2 * ks][3]);
            pk[ks][2] = h2pack(sacc[2 * ks + 1][0], sacc[2 * ks + 1][1]);
            pk[ks][3] = h2pack(sacc[2 * ks + 1][2], sacc[2 * ks + 1][3]);
        }

        // --- O += P @ V ---
#pragma unroll
        for (int ks = 0; ks < 4; ks++) {
            uint32_t vf[4][4];
#pragma unroll
            for (int dp = 0; dp < 4; dp++)
                ldmx4t(vf[dp], smem_u32(&Vb[(16 * ks + ((lane >> 3) & 1) * 8 + (lane & 7)) * AST
                                            + 16 * dp + ((lane >> 4) << 3)]));
#pragma unroll
            for (int dt = 0; dt < 8; dt++)
                mma16816(oacc[dt], pk[ks][0], pk[ks][1], pk[ks][2], pk[ks][3],
                         vf[dt >> 1][(dt & 1) * 2], vf[dt >> 1][(dt & 1) * 2 + 1]);
        }
        __syncthreads();
    }

    l0r += __shfl_xor_sync(0xffffffffu, l0r, 1);
    l0r += __shfl_xor_sync(0xffffffffu, l0r, 2);
    l1r += __shfl_xor_sync(0xffffffffu, l1r, 1);
    l1r += __shfl_xor_sync(0xffffffffu, l1r, 2);
    const float inv0 = 1.f / l0r;
    const float inv1 = 1.f / l1r;

    const size_t orow0 = (size_t)b * NN + qb + wq + g;
#pragma unroll
    for (int dt = 0; dt < 8; dt++) {
        const int n = h * HD + dt * 8 + 2 * t;
        *(uint32_t*)&g_Oh[orow0 * DIMC + n] =
            h2pack(oacc[dt][0] * inv0, oacc[dt][1] * inv0);
        *(uint32_t*)&g_Oh[(orow0 + 8) * DIMC + n] =
            h2pack(oacc[dt][2] * inv1, oacc[dt][3] * inv1);
    }
}

// ---------------------------------------------------------------------------
// Launch
// ---------------------------------------------------------------------------
extern "C" void kernel_launch(void* const* d_in, const int* in_sizes, int n_in,
                              void* d_out, int out_size)
{
    const float* x    = (const float*)d_in[0];
    const float* Wq   = (const float*)d_in[3];
    const float* Wkv  = (const float*)d_in[4];
    const float* Wsr  = (const float*)d_in[5];
    const float* bsr  = (const float*)d_in[6];
    const float* ln_g = (const float*)d_in[7];
    const float* ln_b = (const float*)d_in[8];
    const float* Wp   = (const float*)d_in[9];
    const float* bp   = (const float*)d_in[10];
    float* out = (float*)d_out;

    cudaFuncSetAttribute(attn_h, cudaFuncAttributeMaxDynamicSharedMemorySize,
                         ATT_SMEM_BYTES);

    // 0) fp16 conversions
    auto cvt = [&](const float* src, int id, int n) {
        f2h<<<(n / 4 + 255) / 256, 256>>>(src, id, n);
    };
    cvt(x,   1, BATCH * NN * DIMC);
    cvt(Wsr, 6, DIMC * KSR);
    cvt(Wkv, 7, 2 * DIMC * DIMC);
    cvt(Wq,  8, DIMC * DIMC);
    cvt(Wp,  9, DIMC * DIMC);

    // 1) patches (fp16)
    gather_patches<<<(BATCH * NP * DIMC + 255) / 256, 256>>>(x);

    // 2) SR conv: Xsr = Ph @ Wsr^T + bsr  -> fp32
    hgemm<<<dim3(DIMC / 128, BATCH * NP / 128), 256>>>(
        0, 6, bsr, 1.f, 0, -1, nullptr, BATCH * NP, DIMC, KSR);

    // 3) LayerNorm -> fp16
    ln_rows<<<BATCH * NP, 128>>>(ln_g, ln_b);

    // 4) KV = Xn @ Wkv^T -> fp16
    hgemm<<<dim3(2 * DIMC / 128, BATCH * NP / 128), 256>>>(
        2, 7, nullptr, 1.f, 1, 3, nullptr, BATCH * NP, 2 * DIMC, DIMC);

    // 5) Q = 0.125 * (x @ Wq^T) -> fp16 (scale folded)
    hgemm<<<dim3(DIMC / 128, BATCH * NN / 128), 256>>>(
        1, 8, nullptr, 0.125f, 1, 4, nullptr, BATCH * NN, DIMC, DIMC);

    // 6) attention
    attn_h<<<dim3(NN / 128, NHEAD, BATCH), 256, ATT_SMEM_BYTES>>>();

    // 7) out = O @ Wp^T + bp -> fp32
    hgemm<<<dim3(DIMC / 128, BATCH * NN / 128), 256>>>(
        5, 9, bp, 1.f, 0, -1, out, BATCH * NN, DIMC, DIMC);
}